// round 2
// baseline (speedup 1.0000x reference)
#include <cuda_runtime.h>
#include <cuda_bf16.h>
#include <math.h>

#define BB 64
#define QQ 2048
#define GG 64
#define CC 128
#define NT 256   // lsa threads

// ---------------- device scratch (static, no allocation) ----------------
__device__ double g_cost[BB][GG][QQ];          // 64 MB: cost[b][g][q] (row=gt, col=query)
__device__ int    g_pred[BB][GG];              // matched query per (b,g)
__device__ double g_part_cls[512];
__device__ double g_part_corr[BB];
__device__ double g_part_bbox[BB];
__device__ double g_part_xyz[BB];
__device__ int    g_part_acc[BB];

__constant__ double c_norm[10] = {1.0, 1.0, 1.0, (double)0.1f, (double)0.1f,
                                  (double)0.1f, 1.0, 1.0, (double)0.1f, (double)0.1f};
__constant__ float  c_normf[10] = {1.0f, 1.0f, 1.0f, 0.1f, 0.1f,
                                   0.1f, 1.0f, 1.0f, 0.1f, 0.1f};

// ---------------- phase 1: cost matrix, q-tiled (pn in registers) ----------------
__global__ __launch_bounds__(256) void cost_kernel(const float* __restrict__ cs,
                                                   const float* __restrict__ bp,
                                                   const int* __restrict__ gl,
                                                   const float* __restrict__ gb) {
    const int b = blockIdx.x >> 3;          // 8 tiles of 256 q per batch
    const int q = (blockIdx.x & 7) * 256 + threadIdx.x;
    __shared__ double gn[GG][10];
    __shared__ int    lab[GG];
    for (int t = threadIdx.x; t < GG * 10; t += 256) {
        int g = t / 10, k = t % 10;
        double v = (double)gb[(b * GG + g) * 10 + k] / c_norm[k];
        gn[g][k] = fmin(fmax(v, -100.0), 100.0);
    }
    if (threadIdx.x < GG) lab[threadIdx.x] = gl[b * GG + threadIdx.x];
    __syncthreads();

    double pn[10];
    const float* bq = bp + (size_t)(b * QQ + q) * 10;
#pragma unroll
    for (int k = 0; k < 10; ++k) {
        double v = (double)bq[k] / c_norm[k];
        pn[k] = fmin(fmax(v, -100.0), 100.0);
    }
    const float* csq = cs + (size_t)(b * QQ + q) * CC;
    for (int g = 0; g < GG; ++g) {
        double x = (double)csq[lab[g]];
        x = fmin(fmax(x, -20.0), 20.0);
        double prob = 1.0 / (1.0 + exp(-x));
        double d0 = fabs(pn[0] - gn[g][0]), d1 = fabs(pn[1] - gn[g][1]);
        double d2 = fabs(pn[2] - gn[g][2]), d3 = fabs(pn[3] - gn[g][3]);
        double d4 = fabs(pn[4] - gn[g][4]), d5 = fabs(pn[5] - gn[g][5]);
        double d6 = fabs(pn[6] - gn[g][6]), d7 = fabs(pn[7] - gn[g][7]);
        double d8 = fabs(pn[8] - gn[g][8]), d9 = fabs(pn[9] - gn[g][9]);
        // numpy pairwise order for n=10: r0=d0+d8, r1=d1+d9, ((r0+r1)+(d2+d3))+((d4+d5)+(d6+d7))
        double r0 = d0 + d8, r1 = d1 + d9;
        double s = ((r0 + r1) + (d2 + d3)) + ((d4 + d5) + (d6 + d7));
        g_cost[b][g][q] = 2.0 * (-prob) + 0.25 * s;
    }
}

// ---------------- phase 2: focal loss, all-negative form (no match needed) ----------------
__global__ __launch_bounds__(256) void losscls_kernel(const float* __restrict__ cs) {
    int t = blockIdx.x * 256 + threadIdx.x;      // (b,q) flattened
    const float4* row = (const float4*)(cs + (size_t)t * CC);
    double acc = 0.0;
#pragma unroll 4
    for (int k = 0; k < CC / 4; ++k) {
        float4 v = row[k];
        float xs[4] = {v.x, v.y, v.z, v.w};
#pragma unroll
        for (int u4 = 0; u4 < 4; ++u4) {
            float x = xs[u4];
            float e = __expf(-fabsf(x));
            float inv = 1.0f / (1.0f + e);
            float lp = log1pf(e);
            float p = (x >= 0.0f) ? inv : e * inv;        // sigmoid(x)
            float softp = (x > 0.0f) ? (x + lp) : lp;     // softplus(x)
            acc += (double)(softp * (0.75f * (p * p)));   // all-negative term
        }
    }
    for (int off = 16; off; off >>= 1) acc += __shfl_down_sync(0xffffffffu, acc, off);
    __shared__ double ws[8];
    int lane = threadIdx.x & 31, warp = threadIdx.x >> 5;
    if (lane == 0) ws[warp] = acc;
    __syncthreads();
    if (threadIdx.x == 0) {
        double s = 0.0;
        for (int w = 0; w < 8; ++w) s += ws[w];
        g_part_cls[blockIdx.x] = s;
    }
}

// ---------------- phase 3: Jonker-Volgenant LSA, one CTA per batch ----------------
__global__ __launch_bounds__(NT) void lsa_kernel() {
    const int b = blockIdx.x;
    const int tid = threadIdx.x;
    const int lane = tid & 31, warp = tid >> 5;

    __shared__ double sv[QQ + 1];
    __shared__ double sminv[QQ + 1];
    __shared__ double su[GG + 1];
    __shared__ unsigned char sstamp[QQ + 1];     // phase stamp (row index), never cleared
    __shared__ short  sp[QQ + 1];
    __shared__ short  sway[QQ + 1];
    __shared__ short  slist[256];
    __shared__ int    scnt, sj0, si0, sdone;
    __shared__ double sdelta;
    __shared__ double rv[NT / 32];
    __shared__ int    ri[NT / 32];

    for (int j = tid; j <= QQ; j += NT) { sv[j] = 0.0; sp[j] = 0; sstamp[j] = 0; }
    if (tid <= GG) su[tid] = 0.0;
    __syncthreads();

    const double* __restrict__ costb = &g_cost[b][0][0];

    for (int i = 1; i <= GG; ++i) {
        if (tid == 0) { sj0 = 0; si0 = i; scnt = 1; slist[0] = 0; sp[0] = (short)i; sdone = 0; }
        __syncthreads();
        bool first = true;
        for (;;) {
            const int i0 = si0;
            const int j0c = sj0;
            const double ui0 = su[i0];
            const double dprev = sdelta;          // unused on first iteration
            const int cnt = scnt;
            const double* arow = costb + (size_t)(i0 - 1) * QQ;

            double bv = 1e30; int bj = QQ + 2;
#pragma unroll
            for (int rep = 0; rep < QQ / NT; ++rep) {
                int j = tid + 1 + rep * NT;
                if (sstamp[j] == (unsigned char)i) continue;      // used this phase
                double mv = first ? 1e18 : (sminv[j] - dprev);    // folded minv -= delta
                double cur = (arow[j - 1] - ui0) - sv[j];
                if (cur < mv) { mv = cur; sway[j] = (short)j0c; }
                sminv[j] = mv;
                if (mv < bv) { bv = mv; bj = j; }                 // ascending j per thread
            }
            // lexicographic (value, index) argmin == numpy first-occurrence
            for (int off = 16; off; off >>= 1) {
                double ov = __shfl_down_sync(0xffffffffu, bv, off);
                int    oj = __shfl_down_sync(0xffffffffu, bj, off);
                if (ov < bv || (ov == bv && oj < bj)) { bv = ov; bj = oj; }
            }
            if (lane == 0) { rv[warp] = bv; ri[warp] = bj; }
            __syncthreads();
            if (warp == 0) {
                bv = (lane < NT / 32) ? rv[lane] : 1e30;
                bj = (lane < NT / 32) ? ri[lane] : QQ + 2;
#pragma unroll
                for (int off = (NT / 64); off; off >>= 1) {
                    double ov = __shfl_down_sync(0xffffffffu, bv, off);
                    int    oj = __shfl_down_sync(0xffffffffu, bj, off);
                    if (ov < bv || (ov == bv && oj < bj)) { bv = ov; bj = oj; }
                }
                if (lane == 0) {
                    sdelta = bv; sj0 = bj; si0 = sp[bj];
                    sdone = (sp[bj] == 0);
                }
            }
            __syncthreads();
            const double del = sdelta;
            const int fin = sdone;
            // u/v updates over the OLD used set (matches reference order; runs on final iter too)
            for (int t = tid; t < cnt; t += NT) {
                int jj = slist[t];
                su[sp[jj]] += del;
                sv[jj] -= del;
            }
            if (tid == NT - 1 && !fin) {          // bookkeeping for next iteration
                int j1 = sj0;
                sstamp[j1] = (unsigned char)i;
                if (cnt < 256) slist[cnt] = (short)j1;
                scnt = cnt + 1;
            }
            __syncthreads();
            if (fin) break;
            first = false;
        }
        if (tid == 0) {                           // augment along way[] chain
            int j0 = sj0;
            while (j0) { int jn = sway[j0]; sp[j0] = sp[jn]; j0 = jn; }
        }
        __syncthreads();
    }
    for (int j = tid + 1; j <= QQ; j += NT) {
        int pj = sp[j];
        if (pj) g_pred[b][pj - 1] = j - 1;
    }
}

// ---------------- phase 4: bbox losses + focal correction (pos - neg) ----------------
__global__ void bbox_kernel(const float* __restrict__ cs, const float* __restrict__ bp,
                            const int* __restrict__ gl, const float* __restrict__ gb) {
    int b = blockIdx.x, g = threadIdx.x;   // 64 threads
    int q = g_pred[b][g];
    int lab = gl[b * GG + g];
    const float* mp = bp + (size_t)(b * QQ + q) * 10;
    const float* mg = gb + (size_t)(b * GG + g) * 10;
    double sb = 0.0, sx = 0.0;
#pragma unroll
    for (int k = 0; k < 10; ++k) {
        float a = mp[k], c2 = mg[k];
        float nr = c_normf[k];
        sb += (double)fabsf(a / nr - c2 / nr);
        if (k < 3) sx += (double)fabsf(a - c2);
    }
    const float* r = cs + (size_t)(b * QQ + q) * CC;
    float best = r[0];
    int bi = 0;
    for (int c2 = 1; c2 < CC; ++c2) { float v = r[c2]; if (v > best) { best = v; bi = c2; } }
    int ok = (bi == lab) ? 1 : 0;

    // focal correction for the matched element: pos term replaces neg term
    float x = r[lab];
    float e = __expf(-fabsf(x));
    float inv = 1.0f / (1.0f + e);
    float lp = log1pf(e);
    float p = (x >= 0.0f) ? inv : e * inv;
    float softp = (x > 0.0f) ? (x + lp) : lp;     // softplus(x)  -- identical to losscls
    float softm = (x > 0.0f) ? lp : (lp - x);     // softplus(-x)
    float om = 1.0f - p;
    float neg = softp * (0.75f * (p * p));
    float pos = softm * (0.25f * (om * om));
    double corr = (double)pos - (double)neg;

    int lane = threadIdx.x & 31, warp = threadIdx.x >> 5;
    for (int off = 16; off; off >>= 1) {
        sb += __shfl_down_sync(0xffffffffu, sb, off);
        sx += __shfl_down_sync(0xffffffffu, sx, off);
        corr += __shfl_down_sync(0xffffffffu, corr, off);
        ok += __shfl_down_sync(0xffffffffu, ok, off);
    }
    __shared__ double wsb[2], wsx[2], wsc[2];
    __shared__ int wok[2];
    if (lane == 0) { wsb[warp] = sb; wsx[warp] = sx; wsc[warp] = corr; wok[warp] = ok; }
    __syncthreads();
    if (threadIdx.x == 0) {
        g_part_bbox[b] = wsb[0] + wsb[1];
        g_part_xyz[b]  = wsx[0] + wsx[1];
        g_part_corr[b] = wsc[0] + wsc[1];
        g_part_acc[b]  = wok[0] + wok[1];
    }
}

// ---------------- phase 5: final combine ----------------
__global__ void final_kernel(float* __restrict__ out) {
    int lane = threadIdx.x;   // 32 threads
    double s = 0.0;
    for (int k = lane; k < 512; k += 32) s += g_part_cls[k];
    double corr = 0.0, sb = 0.0, sx = 0.0;
    double ac = 0.0;
    for (int k = lane; k < BB; k += 32) {
        corr += g_part_corr[k]; sb += g_part_bbox[k]; sx += g_part_xyz[k];
        ac += (double)g_part_acc[k];
    }
    for (int off = 16; off; off >>= 1) {
        s    += __shfl_down_sync(0xffffffffu, s, off);
        corr += __shfl_down_sync(0xffffffffu, corr, off);
        sb   += __shfl_down_sync(0xffffffffu, sb, off);
        sx   += __shfl_down_sync(0xffffffffu, sx, off);
        ac   += __shfl_down_sync(0xffffffffu, ac, off);
    }
    if (lane == 0) {
        out[0] = (float)((s + corr) / 4096.0);
        out[1] = (float)(sb / 40960.0);
        out[2] = 64.0f;
        out[3] = (float)(ac / 4096.0);
        out[4] = (float)(sx / 12288.0);
    }
}

// ---------------- launch ----------------
extern "C" void kernel_launch(void* const* d_in, const int* in_sizes, int n_in,
                              void* d_out, int out_size) {
    const float* cs = (const float*)d_in[0];   // (64,2048,128) f32
    const float* bp = (const float*)d_in[1];   // (64,2048,10)  f32
    const int*   gl = (const int*)d_in[2];     // (64,64)       i32
    const float* gb = (const float*)d_in[3];   // (64,64,10)    f32
    float* out = (float*)d_out;

    cost_kernel<<<BB * 8, 256>>>(cs, bp, gl, gb);
    losscls_kernel<<<(BB * QQ) / 256, 256>>>(cs);
    lsa_kernel<<<BB, NT>>>();
    bbox_kernel<<<BB, GG>>>(cs, bp, gl, gb);
    final_kernel<<<1, 32>>>(out);
}

// round 3
// speedup vs baseline: 6.0064x; 6.0064x over previous
#include <cuda_runtime.h>
#include <math.h>

#define BB 64
#define QQ 2048
#define GG 64
#define CC 128
#define NT 512           // lsa threads
#define REPS (QQ/NT)

#define SCALE36 68719476736.0f      // 2^36
#define SCALE38 274877906944.0f     // 2^38
#define INF64 (1LL<<50)

// ---------------- device scratch (static, no allocation) ----------------
__device__ long long g_cost[BB][GG][QQ];   // quantized cost, scale 2^36
__device__ long long g_gq[BB][GG * 10];    // quantized gt bbox, scale 2^38
__device__ int       g_pred[BB][GG];
__device__ float     g_part_cls[512];
__device__ double    g_part_bbox[128], g_part_xyz[128], g_part_corr[128];
__device__ int       g_part_acc[128];

__constant__ float c_normf[10] = {1.0f, 1.0f, 1.0f, 0.1f, 0.1f,
                                  0.1f, 1.0f, 1.0f, 0.1f, 0.1f};

// normalize+clip+quantize a bbox element (double-float, FP32 pipe only)
__device__ __forceinline__ long long quant_bbox(float x, int k) {
    const double RD = 1.0 / (double)0.1f;          // compile-time folded
    const float Rh = (float)RD;
    const float Rl = (float)(RD - (double)Rh);
    float mh, ml;
    bool scaled = (k == 3 || k == 4 || k == 5 || k == 8 || k == 9);
    if (scaled) {
        mh = x * Rh;
        ml = fmaf(x, Rh, -mh);
        ml = fmaf(x, Rl, ml);
    } else { mh = x; ml = 0.0f; }
    if (mh > 100.0f)  { mh = 100.0f;  ml = 0.0f; }
    if (mh < -100.0f) { mh = -100.0f; ml = 0.0f; }
    return __float2ll_rn(mh * SCALE38) + __float2ll_rn(ml * SCALE38);
}

// ---------------- phase 0: quantize gt bboxes ----------------
__global__ void gq_kernel(const float* __restrict__ gb) {
    int b = blockIdx.x, t = threadIdx.x;           // 640 threads
    int k = t % 10;
    g_gq[b][t] = quant_bbox(gb[b * GG * 10 + t], k);
}

// ---------------- phase 1: cost matrix (df exp + int64 L1), no FP64 ----------------
__global__ __launch_bounds__(256) void cost_kernel(const float* __restrict__ cs,
                                                   const float* __restrict__ bp,
                                                   const int* __restrict__ gl) {
    const int b = blockIdx.x >> 3;
    const int q = (blockIdx.x & 7) * 256 + threadIdx.x;
    __shared__ long long sgq[GG * 10];
    __shared__ int slab[GG];
    __shared__ float sTh[64], sTl[64];
    int t = threadIdx.x;
    if (t < 64) {                                   // 2^(t/64) as df (setup only)
        double e2 = exp2((double)t * 0.015625);
        float hv = (float)e2;
        sTh[t] = hv; sTl[t] = (float)(e2 - (double)hv);
    }
    for (int u = t; u < GG * 10; u += 256) sgq[u] = g_gq[b][u];
    if (t < GG) slab[t] = gl[b * GG + t];
    __syncthreads();

    long long pnq[10];
    const float* bq = bp + (size_t)(b * QQ + q) * 10;
#pragma unroll
    for (int k = 0; k < 10; ++k) pnq[k] = quant_bbox(bq[k], k);

    const float* row = cs + (size_t)(b * QQ + q) * CC;
    long long* outp = &g_cost[b][0][q];

    const double C2D = 4.991591397704596e-7;        // ln2/64 - C1
    const float c2h = (float)C2D;
    const float c2l = (float)(C2D - (double)c2h);

    for (int g = 0; g < GG; ++g) {
        float xf = __ldg(row + slab[g]);
        xf = fminf(fmaxf(xf, -20.0f), 20.0f);
        float y = -xf;                              // want exp(-x)
        // --- df exp(y), y in [-20,20] ---
        float kf = rintf(y * 92.332482f);           // 64*log2(e)
        int k2 = (int)kf;
        float r1 = fmaf(kf, -0.010829925537109375f, y);   // exact (13-bit C1)
        float ph = kf * c2h;
        float pl = fmaf(kf, c2h, -ph);              // exact product tail
        float bneg = -ph;                           // TwoSum(r1, -ph)
        float s  = r1 + bneg;
        float tt = s - r1;
        float er = (r1 - (s - tt)) + (bneg - tt);
        float rh = s;
        float rl = er - pl - kf * c2l;              // |r| <= 0.00545
        float t2h = rh * rh;
        float t2l = fmaf(rh, rh, -t2h);
        t2l = fmaf(2.0f * rh, rl, t2l);
        float tail = (t2h * rh) *
            fmaf(rh, 0.041666668f, fmaf(t2h, 0.0083333338f, 0.16666667f));
        float h2 = 0.5f * t2h;
        float Ph = rh + h2;                         // Fast2Sum (|rh|>=|h2|)
        float Pe = (rh - Ph) + h2;
        float Pl = Pe + rl + 0.5f * t2l + tail;
        float Eh = 1.0f + Ph;                       // Fast2Sum with 1
        float El = ((1.0f - Eh) + Ph) + Pl;
        int n = k2 >> 6, j = k2 & 63;
        float th = sTh[j], tl = sTl[j];
        float mh2 = th * Eh;
        float ml2 = fmaf(th, Eh, -mh2);
        ml2 = fmaf(th, El, ml2);
        ml2 = fmaf(tl, Eh, ml2);
        float sc = __int_as_float((n + 127) << 23); // exact 2^n
        float eh = mh2 * sc, el = ml2 * sc;         // e = exp(-x) df
        // --- prob = 1/(1+e) df ---
        float dh = 1.0f + eh;                       // TwoSum(1, eh)
        float t3 = dh - 1.0f;
        float dl = ((1.0f - (dh - t3)) + (eh - t3)) + el;
        float q0 = 1.0f / dh;
        float w  = fmaf(q0, dh, -1.0f);             // exact residual
        w = fmaf(q0, dl, w);
        float probl = q0 * (w * w - w);             // df correction
        // cost_cls = -2*prob, quantized at 2^36 (exact power-of-2 scales)
        long long cq = __float2ll_rn(q0 * (-2.0f * SCALE36)) +
                       __float2ll_rn(probl * (-2.0f * SCALE36));
        // L1 part: exact int64
        const long long* gq = &sgq[g * 10];
        long long l1 = 0;
#pragma unroll
        for (int k = 0; k < 10; ++k) {
            long long d = pnq[k] - gq[k];
            l1 += (d < 0) ? -d : d;
        }
        outp[(size_t)g * QQ] = cq + (l1 >> 2);      // 0.25 * L1 (2^38 -> 2^36)
    }
}

// ---------------- phase 2: focal loss, all-negative form (f32 accum) ----------------
__global__ __launch_bounds__(256) void losscls_kernel(const float* __restrict__ cs) {
    int t = blockIdx.x * 256 + threadIdx.x;
    const float4* row = (const float4*)(cs + (size_t)t * CC);
    float acc = 0.0f;
#pragma unroll 4
    for (int k = 0; k < CC / 4; ++k) {
        float4 v = row[k];
        float xs[4] = {v.x, v.y, v.z, v.w};
#pragma unroll
        for (int u4 = 0; u4 < 4; ++u4) {
            float x = xs[u4];
            float e = __expf(-fabsf(x));
            float inv = 1.0f / (1.0f + e);
            float lp = log1pf(e);
            float p = (x >= 0.0f) ? inv : e * inv;        // sigmoid(x)
            float softp = (x > 0.0f) ? (x + lp) : lp;     // softplus(x)
            acc += softp * (0.75f * (p * p));
        }
    }
    for (int off = 16; off; off >>= 1) acc += __shfl_down_sync(0xffffffffu, acc, off);
    __shared__ float ws[8];
    int lane = threadIdx.x & 31, warp = threadIdx.x >> 5;
    if (lane == 0) ws[warp] = acc;
    __syncthreads();
    if (threadIdx.x == 0) {
        float ssum = 0.0f;
        for (int w = 0; w < 8; ++w) ssum += ws[w];
        g_part_cls[blockIdx.x] = ssum;
    }
}

// ---------------- phase 3: JV LSA, exact int64, one CTA per batch ----------------
__global__ __launch_bounds__(NT) void lsa_kernel() {
    const int b = blockIdx.x, tid = threadIdx.x;
    const int lane = tid & 31, warp = tid >> 5;

    __shared__ long long sv[QQ + 1];
    __shared__ long long sminv[QQ + 1];
    __shared__ long long su[GG + 1];
    __shared__ short sp[QQ + 1];
    __shared__ short sway[QQ + 1];
    __shared__ short slist[QQ + 1];
    __shared__ unsigned char sstamp[QQ + 1];
    __shared__ long long rp[NT / 32];
    __shared__ long long sdelta;
    __shared__ int scnt, sj0, si0, sdone;

    for (int j = tid; j <= QQ; j += NT) { sv[j] = 0; sp[j] = 0; sstamp[j] = 0; }
    if (tid <= GG) su[tid] = 0;
    if (tid == 0) sdelta = 0;
    __syncthreads();

    const long long* __restrict__ costb = &g_cost[b][0][0];

    for (int i = 1; i <= GG; ++i) {
        if (tid == 0) { sj0 = 0; si0 = i; scnt = 1; slist[0] = 0; sp[0] = (short)i; sdone = 0; }
        __syncthreads();
        bool first = true;
        for (;;) {
            const int i0 = si0, j0c = sj0, cnt = scnt;
            const long long ui0 = su[i0];
            const long long dpre = first ? 0 : sdelta;
            const long long* arow = costb + (size_t)(i0 - 1) * QQ;
            long long av[REPS];
#pragma unroll
            for (int rep = 0; rep < REPS; rep++) av[rep] = __ldg(arow + tid + rep * NT);
            long long best = (1LL << 62);
#pragma unroll
            for (int rep = 0; rep < REPS; rep++) {
                int j = tid + 1 + rep * NT;
                if (sstamp[j] == (unsigned char)i) continue;
                long long mv = first ? INF64 : (sminv[j] - dpre);  // folded minv-=delta
                long long cur = av[rep] - ui0 - sv[j];
                if (cur < mv) { mv = cur; sway[j] = (short)j0c; }
                sminv[j] = mv;
                long long pk = (mv << 12) | (long long)j;          // lex (value, j)
                best = (pk < best) ? pk : best;
            }
#pragma unroll
            for (int off = 16; off; off >>= 1) {
                long long o = __shfl_down_sync(0xffffffffu, best, off);
                best = (o < best) ? o : best;
            }
            if (lane == 0) rp[warp] = best;
            __syncthreads();
            if (warp == 0) {
                best = (lane < NT / 32) ? rp[lane] : (1LL << 62);
#pragma unroll
                for (int off = (NT / 64); off; off >>= 1) {
                    long long o = __shfl_down_sync(0xffffffffu, best, off);
                    best = (o < best) ? o : best;
                }
                if (lane == 0) {
                    long long d = best >> 12;
                    int j1 = (int)(best & 4095);
                    sdelta = d; sj0 = j1; si0 = sp[j1];
                    sdone = (sp[j1] == 0);
                }
            }
            __syncthreads();
            const long long del = sdelta;
            const int fin = sdone;
            for (int tt = tid; tt < cnt; tt += NT) {   // exact int updates, old used set
                int jj = slist[tt];
                su[sp[jj]] += del;
                sv[jj] -= del;
            }
            if (tid == NT - 1 && !fin) {
                int j1 = sj0;
                sstamp[j1] = (unsigned char)i;
                slist[cnt] = (short)j1;
                scnt = cnt + 1;
            }
            __syncthreads();
            if (fin) break;
            first = false;
        }
        if (tid == 0) {                                // augment along way[]
            int j0 = sj0;
            while (j0) { int jn = sway[j0]; sp[j0] = sp[jn]; j0 = jn; }
        }
        __syncthreads();
    }
#pragma unroll
    for (int rep = 0; rep < REPS; rep++) {
        int j = tid + 1 + rep * NT;
        int pj = sp[j];
        if (pj) g_pred[b][pj - 1] = j - 1;
    }
}

// ---------------- phase 4: bbox losses + focal correction (warp per (b,g)) --------
__global__ __launch_bounds__(1024) void bbox_kernel(const float* __restrict__ cs,
                                                    const float* __restrict__ bp,
                                                    const int* __restrict__ gl,
                                                    const float* __restrict__ gb) {
    int blk = blockIdx.x;            // 0..127
    int b = blk >> 1;
    int warp = threadIdx.x >> 5, lane = threadIdx.x & 31;
    int g = (blk & 1) * 32 + warp;
    int q = g_pred[b][g];
    int lab = gl[b * GG + g];
    const float* r = cs + (size_t)(b * QQ + q) * CC;

    // argmax over 128, numpy first-occurrence
    float best = -INFINITY; int bi = 0;
#pragma unroll
    for (int k = 0; k < 4; ++k) {
        int c = lane + 32 * k;
        float v = r[c];
        if (v > best) { best = v; bi = c; }
    }
    for (int off = 16; off; off >>= 1) {
        float ov = __shfl_down_sync(0xffffffffu, best, off);
        int   oi = __shfl_down_sync(0xffffffffu, bi, off);
        if (ov > best || (ov == best && oi < bi)) { best = ov; bi = oi; }
    }

    double sb = 0.0, sx = 0.0;
    if (lane < 10) {
        float a  = bp[(size_t)(b * QQ + q) * 10 + lane];
        float c2 = gb[(size_t)(b * GG + g) * 10 + lane];
        float nr = c_normf[lane];
        sb = (double)fabsf(a / nr - c2 / nr);
        if (lane < 3) sx = (double)fabsf(a - c2);
    }
    double corr = 0.0;
    if (lane == 0) {                 // focal correction: pos - neg (bitwise same neg as losscls)
        float x = r[lab];
        float e = __expf(-fabsf(x));
        float inv = 1.0f / (1.0f + e);
        float lp = log1pf(e);
        float p = (x >= 0.0f) ? inv : e * inv;
        float softp = (x > 0.0f) ? (x + lp) : lp;
        float softm = (x > 0.0f) ? lp : (lp - x);
        float om = 1.0f - p;
        float neg = softp * (0.75f * (p * p));
        float pos = softm * (0.25f * (om * om));
        corr = (double)pos - (double)neg;
    }
    for (int off = 16; off; off >>= 1) {
        sb   += __shfl_down_sync(0xffffffffu, sb, off);
        sx   += __shfl_down_sync(0xffffffffu, sx, off);
        corr += __shfl_down_sync(0xffffffffu, corr, off);
    }
    __shared__ double shb[32], shx[32], shc[32];
    __shared__ int sha[32];
    if (lane == 0) { shb[warp] = sb; shx[warp] = sx; shc[warp] = corr; sha[warp] = (bi == lab); }
    __syncthreads();
    if (threadIdx.x == 0) {
        double tb = 0, tx = 0, tc = 0; int ta = 0;
        for (int w = 0; w < 32; ++w) { tb += shb[w]; tx += shx[w]; tc += shc[w]; ta += sha[w]; }
        g_part_bbox[blk] = tb; g_part_xyz[blk] = tx; g_part_corr[blk] = tc; g_part_acc[blk] = ta;
    }
}

// ---------------- phase 5: final combine ----------------
__global__ void final_kernel(float* __restrict__ out) {
    int lane = threadIdx.x;   // 32 threads
    double s = 0.0;
    for (int k = lane; k < 512; k += 32) s += (double)g_part_cls[k];
    double corr = 0.0, sb = 0.0, sx = 0.0, ac = 0.0;
    for (int k = lane; k < 128; k += 32) {
        corr += g_part_corr[k]; sb += g_part_bbox[k]; sx += g_part_xyz[k];
        ac += (double)g_part_acc[k];
    }
    for (int off = 16; off; off >>= 1) {
        s    += __shfl_down_sync(0xffffffffu, s, off);
        corr += __shfl_down_sync(0xffffffffu, corr, off);
        sb   += __shfl_down_sync(0xffffffffu, sb, off);
        sx   += __shfl_down_sync(0xffffffffu, sx, off);
        ac   += __shfl_down_sync(0xffffffffu, ac, off);
    }
    if (lane == 0) {
        out[0] = (float)((s + corr) / 4096.0);
        out[1] = (float)(sb / 40960.0);
        out[2] = 64.0f;
        out[3] = (float)(ac / 4096.0);
        out[4] = (float)(sx / 12288.0);
    }
}

// ---------------- launch ----------------
extern "C" void kernel_launch(void* const* d_in, const int* in_sizes, int n_in,
                              void* d_out, int out_size) {
    const float* cs = (const float*)d_in[0];   // (64,2048,128) f32
    const float* bp = (const float*)d_in[1];   // (64,2048,10)  f32
    const int*   gl = (const int*)d_in[2];     // (64,64)       i32
    const float* gb = (const float*)d_in[3];   // (64,64,10)    f32
    float* out = (float*)d_out;

    gq_kernel<<<BB, GG * 10>>>(gb);
    cost_kernel<<<BB * 8, 256>>>(cs, bp, gl);
    losscls_kernel<<<(BB * QQ) / 256, 256>>>(cs);
    lsa_kernel<<<BB, NT>>>();
    bbox_kernel<<<BB * 2, 1024>>>(cs, bp, gl, gb);
    final_kernel<<<1, 32>>>(out);
}